// round 1
// baseline (speedup 1.0000x reference)
#include <cuda_runtime.h>

// Problem constants (fixed by setup_inputs)
#define MROWS 32
#define NCOLS 10000
#define KDIM  10000
#define PDIM  64
#define SPLITS 25
#define KC    400        // KDIM / SPLITS, divisible by KB
#define KB    8
#define BN    256
#define NBLK  40         // ceil(NCOLS/BN)
#define NEPB  79         // ceil(NCOLS/128)

typedef unsigned long long u64;

// Scratch (allocation-free: device globals)
__device__ float g_Wp[MROWS * MROWS];
__device__ float g_B [MROWS * NCOLS];
__device__ float g_Ya[MROWS * NCOLS];
__device__ float g_Yb[MROWS * NCOLS];
__device__ float g_Zp[SPLITS * MROWS * NCOLS];   // split-K partials, [sp][row][col]

__device__ __forceinline__ u64 pack2(float lo, float hi) {
    u64 r; asm("mov.b64 %0, {%1, %2};" : "=l"(r) : "f"(lo), "f"(hi)); return r;
}
__device__ __forceinline__ void unpack2(u64 v, float& lo, float& hi) {
    asm("mov.b64 {%0, %1}, %2;" : "=f"(lo), "=f"(hi) : "l"(v));
}
__device__ __forceinline__ void fma2(u64& d, u64 a, u64 b) {
    asm("fma.rn.f32x2 %0, %1, %2, %0;" : "+l"(d) : "l"(a), "l"(b));
}

// ---------------------------------------------------------------------------
// 1. Row-wise projection of W onto ||row||_1 <= v  (=> ||W||_inf <= v)
//    Exactly mirrors the reference: rows with sum(|a|) <= v untouched.
// ---------------------------------------------------------------------------
__global__ void k_project(const float* __restrict__ W) {
    int r = threadIdx.x;
    if (r >= MROWS) return;
    float a[32], u[32];
    float s = 0.0f;
    for (int i = 0; i < 32; i++) { a[i] = W[r * 32 + i]; u[i] = fabsf(a[i]); s += u[i]; }
    const float v = 0.99f;  // KAPPA / A_RHO
    if (s > v) {
        // insertion sort descending
        for (int i = 1; i < 32; i++) {
            float key = u[i]; int j = i - 1;
            while (j >= 0 && u[j] < key) { u[j + 1] = u[j]; j--; }
            u[j + 1] = key;
        }
        float cs = 0.0f; int rho = 0;
        for (int i = 0; i < 32; i++) {
            cs += u[i];
            if (u[i] - (cs - v) / (float)(i + 1) > 0.0f) rho++;
        }
        float cs2 = 0.0f;
        for (int i = 0; i < rho; i++) cs2 += u[i];
        float theta = (cs2 - v) / (float)rho;
        for (int i = 0; i < 32; i++) {
            float m = fmaxf(fabsf(a[i]) - theta, 0.0f);
            a[i] = (a[i] > 0.0f) ? m : ((a[i] < 0.0f) ? -m : 0.0f);
        }
    }
    for (int i = 0; i < 32; i++) g_Wp[r * 32 + i] = a[i];
}

// ---------------------------------------------------------------------------
// 2. T = Omega_1 @ U   [32,64]x[64,10000] -> g_Ya
// ---------------------------------------------------------------------------
__global__ void k_T(const float* __restrict__ Om1, const float* __restrict__ U) {
    __shared__ float Om[MROWS * PDIM];
    for (int i = threadIdx.x; i < MROWS * PDIM; i += blockDim.x) Om[i] = Om1[i];
    __syncthreads();
    int c = blockIdx.x * blockDim.x + threadIdx.x;
    if (c >= NCOLS) return;
    float uv[PDIM];
    #pragma unroll
    for (int j = 0; j < PDIM; j++) uv[j] = U[(size_t)j * NCOLS + c];
    for (int r = 0; r < MROWS; r++) {
        float sacc = 0.0f;
        #pragma unroll
        for (int j = 0; j < PDIM; j++) sacc += Om[r * PDIM + j] * uv[j];
        g_Ya[r * NCOLS + c] = sacc;
    }
}

// ---------------------------------------------------------------------------
// 3. Split-K GEMM:  Zp[sp] = Y[:, ks:ks+KC] @ A[ks:ks+KC, :]
//    f32x2 packed FMA, A duplicated {a,a} in smem, Y row-pairs from smem.
//    Thread tile: 8 rows (4 f32x2 row-pairs) x 8 strided cols.
// ---------------------------------------------------------------------------
__global__ void __launch_bounds__(128) k_gemm(const float* __restrict__ A, int ysel) {
    const float* __restrict__ Y = ysel ? g_Yb : g_Ya;
    __shared__ __align__(16) float2 Asd[KB][BN];     // 16 KB, duplicated pairs
    __shared__ __align__(16) float  Ys[KB][MROWS];   // 1 KB

    const int t  = threadIdx.x;
    const int nb = blockIdx.x % NBLK;
    const int sp = blockIdx.x / NBLK;
    const int c0 = nb * BN;
    const int ks = sp * KC;
    const int cg = t & 31;       // 32 column groups (cols cg + 32*j)
    const int rg = t >> 5;       // 4 row groups (rows rg*8 .. rg*8+7)

    u64 acc[4][8];
    #pragma unroll
    for (int p = 0; p < 4; p++)
        #pragma unroll
        for (int j = 0; j < 8; j++) acc[p][j] = 0ULL;

    for (int kb = 0; kb < KC / KB; kb++) {
        const int kbase = ks + kb * KB;
        // stage A rows [kbase, kbase+8) x cols [c0, c0+256), duplicated
        #pragma unroll
        for (int q = 0; q < 4; q++) {
            int idx  = t + q * 128;
            int row  = idx >> 6;
            int colq = idx & 63;
            int c    = c0 + colq * 4;
            float4 vv = make_float4(0.f, 0.f, 0.f, 0.f);
            if (c < NCOLS)
                vv = *reinterpret_cast<const float4*>(&A[(size_t)(kbase + row) * NCOLS + c]);
            float4* dst = reinterpret_cast<float4*>(&Asd[row][colq * 4]);
            dst[0] = make_float4(vv.x, vv.x, vv.y, vv.y);
            dst[1] = make_float4(vv.z, vv.z, vv.w, vv.w);
        }
        // stage Y [32 rows] x [8 k]
        #pragma unroll
        for (int q = 0; q < 2; q++) {
            int idx = t + q * 128;
            int kr  = idx >> 5;
            int r   = idx & 31;
            Ys[kr][r] = Y[(size_t)r * NCOLS + kbase + kr];
        }
        __syncthreads();
        #pragma unroll
        for (int kk = 0; kk < KB; kk++) {
            float4 ya = *reinterpret_cast<const float4*>(&Ys[kk][rg * 8]);
            float4 yb = *reinterpret_cast<const float4*>(&Ys[kk][rg * 8 + 4]);
            u64 y0 = pack2(ya.x, ya.y);
            u64 y1 = pack2(ya.z, ya.w);
            u64 y2 = pack2(yb.x, yb.y);
            u64 y3 = pack2(yb.z, yb.w);
            #pragma unroll
            for (int j = 0; j < 8; j++) {
                u64 ad = *reinterpret_cast<const u64*>(&Asd[kk][cg + 32 * j]);
                fma2(acc[0][j], y0, ad);
                fma2(acc[1][j], y1, ad);
                fma2(acc[2][j], y2, ad);
                fma2(acc[3][j], y3, ad);
            }
        }
        __syncthreads();
    }
    // store partials [sp][row][col]
    #pragma unroll
    for (int j = 0; j < 8; j++) {
        int c = c0 + cg + 32 * j;
        if (c < NCOLS) {
            #pragma unroll
            for (int p = 0; p < 4; p++) {
                float lo, hi; unpack2(acc[p][j], lo, hi);
                int row = rg * 8 + 2 * p;
                g_Zp[((size_t)sp * MROWS + row)     * NCOLS + c] = lo;
                g_Zp[((size_t)sp * MROWS + row + 1) * NCOLS + c] = hi;
            }
        }
    }
}

// ---------------------------------------------------------------------------
// 4. Epilogue.
//    it == 0 : B = sum(Zp)                     (b = T @ A)
//    it >= 1 : X = relu((use_z ? sum(Zp) : 0) + B);
//              if it == fw_mitr: write X to out
//              if it <  fw_mitr: Y_next = Wp @ X
// ---------------------------------------------------------------------------
__global__ void k_epilogue(float* __restrict__ Xout, const int* __restrict__ fw,
                           int it, int use_z, int yout_sel) {
    __shared__ float Wps[MROWS * MROWS];
    for (int i = threadIdx.x; i < MROWS * MROWS; i += blockDim.x) Wps[i] = g_Wp[i];
    __syncthreads();
    int c = blockIdx.x * blockDim.x + threadIdx.x;
    if (c >= NCOLS) return;

    if (it == 0) {
        #pragma unroll
        for (int r = 0; r < MROWS; r++) {
            float s = 0.0f;
            #pragma unroll
            for (int sp = 0; sp < SPLITS; sp++)
                s += g_Zp[((size_t)sp * MROWS + r) * NCOLS + c];
            g_B[r * NCOLS + c] = s;
        }
        return;
    }

    int fwv = *fw;
    if (it > fwv) return;

    float x[MROWS];
    #pragma unroll
    for (int r = 0; r < MROWS; r++) {
        float s = g_B[r * NCOLS + c];
        if (use_z) {
            #pragma unroll
            for (int sp = 0; sp < SPLITS; sp++)
                s += g_Zp[((size_t)sp * MROWS + r) * NCOLS + c];
        }
        x[r] = fmaxf(s, 0.0f);
    }
    if (it == fwv) {
        #pragma unroll
        for (int r = 0; r < MROWS; r++) Xout[(size_t)r * NCOLS + c] = x[r];
    }
    if (it < fwv) {
        float* __restrict__ Yout = yout_sel ? g_Yb : g_Ya;
        #pragma unroll
        for (int r = 0; r < MROWS; r++) {
            float s = 0.0f;
            #pragma unroll
            for (int j = 0; j < MROWS; j++) s += Wps[r * MROWS + j] * x[j];
            Yout[(size_t)r * NCOLS + c] = s;
        }
    }
}

// ---------------------------------------------------------------------------
// Launch: project -> T -> (b pass) -> 30 Picard iterations
// Inputs (metadata order): W, Omega_1, Omega_2, X_0, A, U, fw_mitr
// ---------------------------------------------------------------------------
extern "C" void kernel_launch(void* const* d_in, const int* in_sizes, int n_in,
                              void* d_out, int out_size) {
    const float* W   = (const float*)d_in[0];
    const float* Om1 = (const float*)d_in[1];
    // d_in[2] = Omega_2 (unused, as in reference), d_in[3] = X_0 (zeros)
    const float* A   = (const float*)d_in[4];
    const float* U   = (const float*)d_in[5];
    const int*   fw  = (const int*)  d_in[6];
    float*       out = (float*)d_out;

    k_project<<<1, 32>>>(W);
    k_T<<<NEPB, 128>>>(Om1, U);

    // b = T @ A
    k_gemm<<<NBLK * SPLITS, 128>>>(A, 0);
    k_epilogue<<<NEPB, 128>>>(out, fw, 0, 0, 0);

    // it = 1: X1 = relu(b), Y1 = Wp @ X1 -> g_Yb
    k_epilogue<<<NEPB, 128>>>(out, fw, 1, 0, 1);

    // it = 2..30
    for (int it = 2; it <= 30; ++it) {
        k_gemm<<<NBLK * SPLITS, 128>>>(A, (it - 1) & 1);
        k_epilogue<<<NEPB, 128>>>(out, fw, it, 1, it & 1);
    }
}

// round 3
// speedup vs baseline: 1.1050x; 1.1050x over previous
#include <cuda_runtime.h>
#include <cuda_fp16.h>
#include <cstdint>

#define MR     32
#define NCOLS  10000
#define KDIM   10000
#define NB     157        // column blocks of 64 (157*64 = 10048 padded)
#define BN     64
#define KCH    625        // k-chunks of 16 (625*16 = 10000)
#define NPCH   628        // padded chunk count for Y buffers
#define STAGES 3
#define INV2048 (1.0f/2048.0f)

// ---------------- device scratch (allocation-free) ----------------
// Blocked A, fp16 hi/lo: per (nb,kc) chunk: 1024 hi halves [c][kk] then 1024 lo.
__device__ __align__(16) __half g_Apk[(size_t)NB * KCH * 2048];     // ~402 MB
// Y ping-pong, chunked: per kc: 512 hi halves [m][kk] then 512 lo.
__device__ __align__(16) __half g_Yp[2][(size_t)NPCH * 1024];
__device__ float  g_B[NB * BN * MR];
__device__ float  g_Wp[MR * MR];

// ---------------- helpers ----------------
__device__ __forceinline__ void cpa16(uint32_t d, const void* s) {
    asm volatile("cp.async.cg.shared.global [%0], [%1], 16;" :: "r"(d), "l"(s));
}
__device__ __forceinline__ void ldm4(uint32_t* r, uint32_t a) {
    asm volatile("ldmatrix.sync.aligned.m8n8.x4.shared.b16 {%0,%1,%2,%3}, [%4];"
        : "=r"(r[0]), "=r"(r[1]), "=r"(r[2]), "=r"(r[3]) : "r"(a));
}
__device__ __forceinline__ void mma_(float* c, const uint32_t* a, uint32_t b0, uint32_t b1) {
    asm volatile("mma.sync.aligned.m16n8k16.row.col.f32.f16.f16.f32 "
        "{%0,%1,%2,%3}, {%4,%5,%6,%7}, {%8,%9}, {%0,%1,%2,%3};"
        : "+f"(c[0]), "+f"(c[1]), "+f"(c[2]), "+f"(c[3])
        : "r"(a[0]), "r"(a[1]), "r"(a[2]), "r"(a[3]), "r"(b0), "r"(b1));
}
__device__ __forceinline__ void hilo(float v, __half& h, __half& l) {
    h = __float2half_rn(v);
    l = __float2half_rn((v - __half2float(h)) * 2048.0f);
}

// ---------------- 1. W projection (verified in R1) ----------------
__global__ void k_project(const float* __restrict__ W) {
    int r = threadIdx.x;
    if (r >= MR) return;
    float a[32], u[32];
    float s = 0.0f;
    for (int i = 0; i < 32; i++) { a[i] = W[r * 32 + i]; u[i] = fabsf(a[i]); s += u[i]; }
    const float v = 0.99f;
    if (s > v) {
        for (int i = 1; i < 32; i++) {
            float key = u[i]; int j = i - 1;
            while (j >= 0 && u[j] < key) { u[j + 1] = u[j]; j--; }
            u[j + 1] = key;
        }
        float cs = 0.0f; int rho = 0;
        for (int i = 0; i < 32; i++) {
            cs += u[i];
            if (u[i] - (cs - v) / (float)(i + 1) > 0.0f) rho++;
        }
        float cs2 = 0.0f;
        for (int i = 0; i < rho; i++) cs2 += u[i];
        float theta = (cs2 - v) / (float)rho;
        for (int i = 0; i < 32; i++) {
            float m = fmaxf(fabsf(a[i]) - theta, 0.0f);
            a[i] = (a[i] > 0.0f) ? m : ((a[i] < 0.0f) ? -m : 0.0f);
        }
    }
    for (int i = 0; i < 32; i++) g_Wp[r * 32 + i] = a[i];
}

// ---------------- 2. Convert A -> blocked fp16 hi/lo ----------------
__global__ void k_convA(const float* __restrict__ A) {
    __shared__ __align__(16) float sA[16][68];
    int b  = blockIdx.x;               // nb*KCH + kc
    int nb = b / KCH, kc = b % KCH;
    int t  = threadIdx.x;
    int k0 = kc * 16, c0 = nb * BN;
    for (int e = t; e < 1024; e += 128) {
        int kk = e >> 6, c = e & 63;          // covers all 16 x 64
        int gc = c0 + c;
        float v0 = 0.0f;
        if (gc < NCOLS) v0 = A[(size_t)(k0 + kk) * NCOLS + gc];
        sA[kk][c] = v0;
    }
    __syncthreads();
    __half* dst = &g_Apk[(size_t)b * 2048];
    for (int e = t; e < 1024; e += 128) {
        int c = e >> 4, kk = e & 15;
        __half h, l; hilo(sA[kk][c], h, l);
        dst[e] = h;
        dst[1024 + e] = l;
    }
}

// ---------------- 3. T = Omega_1 @ U  -> Y[0] chunked hi/lo ----------------
__global__ void k_T(const float* __restrict__ Om1, const float* __restrict__ U) {
    __shared__ float sOm[MR * 64];
    int t = threadIdx.x;
    for (int i = t; i < MR * 64; i += 128) sOm[i] = Om1[i];
    __syncthreads();
    int kc = blockIdx.x;
    __half* dst = &g_Yp[0][(size_t)kc * 1024];
    for (int e = t; e < 512; e += 128) {
        int m = e >> 4, kk = e & 15;
        int k = kc * 16 + kk;
        float v = 0.f;
        #pragma unroll
        for (int p = 0; p < 64; p++) v += sOm[m * 64 + p] * U[(size_t)p * NCOLS + k];
        __half h, l; hilo(v, h, l);
        dst[m * 16 + kk] = h;
        dst[512 + m * 16 + kk] = l;
    }
}

// ---------------- 4. Fused Picard pass ----------------
// Z = Y @ A (this CTA's 64 cols, full K);  then
//   writeB: B = Z ;  useB: Z += B ;  X = relu(Z) ;
//   it==fw: out = X ;  it<fw: Y_next = hilo(Wp @ X)
__global__ void __launch_bounds__(128, 2)
k_iter(const int* __restrict__ fw, float* __restrict__ out,
       int it, int src, int writeB, int useB) {
    __shared__ __align__(16) __half smA[STAGES][2 * 64 * 24];   // [h][c][24] padded
    __shared__ __align__(16) __half smY[STAGES][2 * 32 * 24];   // [h][m][24]
    __shared__ __align__(16) float  sZ[64][33];
    __shared__ float  sWp[MR * MR];

    const int t = threadIdx.x;
    const int nb = blockIdx.x;
    const int w = t >> 5, lane = t & 31;

    const int fwv = *fw;
    if (it > fwv) return;

    for (int i = t; i < MR * MR; i += 128) sWp[i] = g_Wp[i];

    const __half* Asrc = &g_Apk[(size_t)nb * KCH * 2048];
    const __half* Ysrc = g_Yp[src];

    const uint32_t aBase = (uint32_t)__cvta_generic_to_shared(smA);
    const uint32_t yBase = (uint32_t)__cvta_generic_to_shared(smY);
    const uint32_t aStage = 2 * 64 * 24 * 2;   // bytes
    const uint32_t yStage = 2 * 32 * 24 * 2;

    // cp.async granule mapping (3 granules/thread/chunk: 2 A, 1 Y)
    const int gA_c = (t >> 1) & 63, gA_s = t & 1;
    const int gY_h = (t >> 6) & 1,  gY_m = (t >> 1) & 31, gY_s = t & 1;
    const uint32_t dA0 = ((0 * 64 + gA_c) * 24 + gA_s * 8) * 2;
    const uint32_t dA1 = ((1 * 64 + gA_c) * 24 + gA_s * 8) * 2;
    const uint32_t dY  = ((gY_h * 32 + gY_m) * 24 + gY_s * 8) * 2;
    const int sA0 = 0 * 1024 + gA_c * 16 + gA_s * 8;
    const int sA1 = 1 * 1024 + gA_c * 16 + gA_s * 8;
    const int sY  = gY_h * 512 + gY_m * 16 + gY_s * 8;

    // ldmatrix per-lane offsets (in bytes)
    const int tl = lane >> 3, rl = lane & 7;
    const int aRow = w * 16 + ((tl & 1) << 3) + rl;
    const int aKo  = (tl >> 1) << 3;
    const uint32_t offAhi = (uint32_t)((aRow)      * 24 + aKo) * 2;
    const uint32_t offAlo = (uint32_t)((64 + aRow) * 24 + aKo) * 2;
    const int yM  = ((tl >> 1) << 3) + rl;
    const int yKo = (tl & 1) << 3;
    const uint32_t offYh0 = (uint32_t)((yM)           * 24 + yKo) * 2;
    const uint32_t offYh1 = (uint32_t)((yM + 16)      * 24 + yKo) * 2;
    const uint32_t offYl0 = (uint32_t)((32 + yM)      * 24 + yKo) * 2;
    const uint32_t offYl1 = (uint32_t)((32 + yM + 16) * 24 + yKo) * 2;

    auto issue = [&](int kc2) {
        int buf = kc2 % STAGES;
        const __half* ac = Asrc + (size_t)kc2 * 2048;
        const __half* yc = Ysrc + (size_t)kc2 * 1024;
        uint32_t ab = aBase + buf * aStage;
        uint32_t yb = yBase + buf * yStage;
        cpa16(ab + dA0, ac + sA0);
        cpa16(ab + dA1, ac + sA1);
        cpa16(yb + dY,  yc + sY);
    };

    // prologue
    issue(0); asm volatile("cp.async.commit_group;");
    issue(1); asm volatile("cp.async.commit_group;");

    float Cm[4][4], Cs[4][4];
    #pragma unroll
    for (int j = 0; j < 4; j++)
        #pragma unroll
        for (int q = 0; q < 4; q++) { Cm[j][q] = 0.f; Cs[j][q] = 0.f; }

    for (int kc = 0; kc < KCH; kc++) {
        asm volatile("cp.async.wait_group %0;" :: "n"(STAGES - 2));
        __syncthreads();
        int nkc = kc + STAGES - 1;
        if (nkc < KCH) issue(nkc);
        asm volatile("cp.async.commit_group;");

        int buf = kc % STAGES;
        uint32_t ab = aBase + buf * aStage;
        uint32_t yb = yBase + buf * yStage;

        uint32_t Ah[4], Al[4], Bh0[4], Bh1[4], Bl0[4], Bl1[4];
        ldm4(Ah,  ab + offAhi);
        ldm4(Al,  ab + offAlo);
        ldm4(Bh0, yb + offYh0);
        ldm4(Bh1, yb + offYh1);
        ldm4(Bl0, yb + offYl0);
        ldm4(Bl1, yb + offYl1);

        mma_(Cm[0], Ah, Bh0[0], Bh0[1]);
        mma_(Cm[1], Ah, Bh0[2], Bh0[3]);
        mma_(Cm[2], Ah, Bh1[0], Bh1[1]);
        mma_(Cm[3], Ah, Bh1[2], Bh1[3]);

        mma_(Cs[0], Ah, Bl0[0], Bl0[1]);
        mma_(Cs[1], Ah, Bl0[2], Bl0[3]);
        mma_(Cs[2], Ah, Bl1[0], Bl1[1]);
        mma_(Cs[3], Ah, Bl1[2], Bl1[3]);

        mma_(Cs[0], Al, Bh0[0], Bh0[1]);
        mma_(Cs[1], Al, Bh0[2], Bh0[3]);
        mma_(Cs[2], Al, Bh1[0], Bh1[1]);
        mma_(Cs[3], Al, Bh1[2], Bh1[3]);
    }
    asm volatile("cp.async.wait_group 0;");
    __syncthreads();

    // scatter C frags -> sZ[c][m]
    {
        const int g = lane >> 2, i2 = (lane & 3) << 1;
        const int c = w * 16 + g;
        #pragma unroll
        for (int j = 0; j < 4; j++) {
            int m = j * 8 + i2;
            sZ[c][m]         = Cm[j][0] + Cs[j][0] * INV2048;
            sZ[c][m + 1]     = Cm[j][1] + Cs[j][1] * INV2048;
            sZ[c + 8][m]     = Cm[j][2] + Cs[j][2] * INV2048;
            sZ[c + 8][m + 1] = Cm[j][3] + Cs[j][3] * INV2048;
        }
    }
    __syncthreads();

    // epilogue: 2 threads per column (16 rows each)
    const int col = t >> 1, r0 = (t & 1) << 4;
    const int gcol = nb * BN + col;
    float* Bp = &g_B[(nb * BN + col) * MR];
    const bool writeOut = (it == fwv);
    const bool writeY   = (it < fwv);

    #pragma unroll
    for (int r = 0; r < 16; r++) {
        int rr = r0 + r;
        float z = sZ[col][rr];
        if (useB)   z += Bp[rr];
        if (writeB) Bp[rr] = z;
        float xv = fmaxf(z, 0.0f);
        if (writeOut && gcol < NCOLS) out[(size_t)rr * NCOLS + gcol] = xv;
        sZ[col][rr] = xv;
    }
    __syncthreads();

    if (writeY) {
        int kc = gcol >> 4, kk = gcol & 15;
        __half* Yd = g_Yp[src ^ 1] + (size_t)kc * 1024;
        #pragma unroll
        for (int r = 0; r < 16; r++) {
            int rr = r0 + r;
            float y = 0.f;
            #pragma unroll
            for (int j = 0; j < MR; j++) y += sWp[rr * MR + j] * sZ[col][j];
            __half h, l; hilo(y, h, l);
            Yd[rr * 16 + kk] = h;
            Yd[512 + rr * 16 + kk] = l;
        }
    }
}

// ---------------- launch ----------------
// Inputs: W, Omega_1, Omega_2, X_0, A, U, fw_mitr
extern "C" void kernel_launch(void* const* d_in, const int* in_sizes, int n_in,
                              void* d_out, int out_size) {
    const float* W   = (const float*)d_in[0];
    const float* Om1 = (const float*)d_in[1];
    const float* A   = (const float*)d_in[4];
    const float* U   = (const float*)d_in[5];
    const int*   fw  = (const int*)  d_in[6];
    float*       out = (float*)d_out;

    k_project<<<1, 32>>>(W);
    k_convA<<<NB * KCH, 128>>>(A);
    k_T<<<KCH, 128>>>(Om1, U);

    // it = 1: Z = T@A = b ; B := Z ; X1 = relu(b) ; Y1 = Wp@X1
    k_iter<<<NB, 128>>>(fw, out, 1, 0, 1, 0);
    // it = 2..30
    for (int it = 2; it <= 30; it++)
        k_iter<<<NB, 128>>>(fw, out, it, (it - 1) & 1, 0, 1);
}

// round 4
// speedup vs baseline: 1.7567x; 1.5897x over previous
#include <cuda_runtime.h>
#include <cuda_fp16.h>
#include <cstdint>

#define MR     32
#define NCOLS  10000
#define KDIM   10000
#define NB     157        // column blocks of 64 (157*64 = 10048 padded)
#define BN     64
#define KCH    625        // k-chunks of 16 (625*16 = 10000)
#define NPCH   628        // padded chunk count for Y buffers
#define STAGES 4
#define KSPLIT 4
#define STGB   9216       // bytes per pipeline stage (A 6144 + Y 3072)
#define INV2048 (1.0f/2048.0f)

// ---------------- device scratch (allocation-free) ----------------
__device__ __align__(16) __half g_Apk[(size_t)NB * KCH * 2048];     // ~402 MB
__device__ __align__(16) __half g_Yp[2][(size_t)NPCH * 1024];
__device__ __align__(16) float  g_Zp[(size_t)KSPLIT * NB * 2048];   // split-K partials
__device__ float  g_B[NB * BN * MR];
__device__ float  g_Wp[MR * MR];
__device__ int    g_cnt[NB];                                        // zero-init

// ---------------- helpers ----------------
__device__ __forceinline__ void cpa16(uint32_t d, const void* s) {
    asm volatile("cp.async.cg.shared.global [%0], [%1], 16;" :: "r"(d), "l"(s));
}
__device__ __forceinline__ void ldm4(uint32_t* r, uint32_t a) {
    asm volatile("ldmatrix.sync.aligned.m8n8.x4.shared.b16 {%0,%1,%2,%3}, [%4];"
        : "=r"(r[0]), "=r"(r[1]), "=r"(r[2]), "=r"(r[3]) : "r"(a));
}
__device__ __forceinline__ void mma_(float* c, const uint32_t* a, uint32_t b0, uint32_t b1) {
    asm volatile("mma.sync.aligned.m16n8k16.row.col.f32.f16.f16.f32 "
        "{%0,%1,%2,%3}, {%4,%5,%6,%7}, {%8,%9}, {%0,%1,%2,%3};"
        : "+f"(c[0]), "+f"(c[1]), "+f"(c[2]), "+f"(c[3])
        : "r"(a[0]), "r"(a[1]), "r"(a[2]), "r"(a[3]), "r"(b0), "r"(b1));
}
__device__ __forceinline__ void hilo(float v, __half& h, __half& l) {
    h = __float2half_rn(v);
    l = __float2half_rn((v - __half2float(h)) * 2048.0f);
}

// ---------------- 1. W projection (verified) ----------------
__global__ void k_project(const float* __restrict__ W) {
    int r = threadIdx.x;
    if (r >= MR) return;
    float a[32], u[32];
    float s = 0.0f;
    for (int i = 0; i < 32; i++) { a[i] = W[r * 32 + i]; u[i] = fabsf(a[i]); s += u[i]; }
    const float v = 0.99f;
    if (s > v) {
        for (int i = 1; i < 32; i++) {
            float key = u[i]; int j = i - 1;
            while (j >= 0 && u[j] < key) { u[j + 1] = u[j]; j--; }
            u[j + 1] = key;
        }
        float cs = 0.0f; int rho = 0;
        for (int i = 0; i < 32; i++) {
            cs += u[i];
            if (u[i] - (cs - v) / (float)(i + 1) > 0.0f) rho++;
        }
        float cs2 = 0.0f;
        for (int i = 0; i < rho; i++) cs2 += u[i];
        float theta = (cs2 - v) / (float)rho;
        for (int i = 0; i < 32; i++) {
            float m = fmaxf(fabsf(a[i]) - theta, 0.0f);
            a[i] = (a[i] > 0.0f) ? m : ((a[i] < 0.0f) ? -m : 0.0f);
        }
    }
    for (int i = 0; i < 32; i++) g_Wp[r * 32 + i] = a[i];
}

// ---------------- 2. Convert A -> blocked fp16 hi/lo (verified) ----------------
__global__ void k_convA(const float* __restrict__ A) {
    __shared__ __align__(16) float sA[16][68];
    int b  = blockIdx.x;               // nb*KCH + kc
    int nb = b / KCH, kc = b % KCH;
    int t  = threadIdx.x;
    int k0 = kc * 16, c0 = nb * BN;
    for (int e = t; e < 1024; e += 128) {
        int kk = e >> 6, c = e & 63;
        int gc = c0 + c;
        float v0 = 0.0f;
        if (gc < NCOLS) v0 = A[(size_t)(k0 + kk) * NCOLS + gc];
        sA[kk][c] = v0;
    }
    __syncthreads();
    __half* dst = &g_Apk[(size_t)b * 2048];
    for (int e = t; e < 1024; e += 128) {
        int c = e >> 4, kk = e & 15;
        __half h, l; hilo(sA[kk][c], h, l);
        dst[e] = h;
        dst[1024 + e] = l;
    }
}

// ---------------- 3. T = Omega_1 @ U -> Y[0] (verified) ----------------
__global__ void k_T(const float* __restrict__ Om1, const float* __restrict__ U) {
    __shared__ float sOm[MR * 64];
    int t = threadIdx.x;
    for (int i = t; i < MR * 64; i += 128) sOm[i] = Om1[i];
    __syncthreads();
    int kc = blockIdx.x;
    __half* dst = &g_Yp[0][(size_t)kc * 1024];
    for (int e = t; e < 512; e += 128) {
        int m = e >> 4, kk = e & 15;
        int k = kc * 16 + kk;
        float v = 0.f;
        #pragma unroll
        for (int p = 0; p < 64; p++) v += sOm[m * 64 + p] * U[(size_t)p * NCOLS + k];
        __half h, l; hilo(v, h, l);
        dst[m * 16 + kk] = h;
        dst[512 + m * 16 + kk] = l;
    }
}

// ---------------- 4. Fused Picard pass, split-K x4 + atomic-ticket epilogue ----
__global__ void __launch_bounds__(128, 4)
k_iter(const int* __restrict__ fw, float* __restrict__ out,
       int it, int src, int writeB, int useB) {
    __shared__ __align__(16) unsigned char sBuf[STAGES * STGB];  // pipeline / sZ overlay
    __shared__ float sWp[MR * MR];
    __shared__ int   sLast;

    const int t = threadIdx.x;
    const int nb = blockIdx.x % NB;
    const int sp = blockIdx.x / NB;
    const int w = t >> 5, lane = t & 31;

    const int fwv = *fw;
    if (it > fwv) return;

    for (int i = t; i < MR * MR; i += 128) sWp[i] = g_Wp[i];

    const int kbeg = (sp * KCH) / KSPLIT;
    const int kend = ((sp + 1) * KCH) / KSPLIT;

    const __half* Asrc = &g_Apk[(size_t)nb * KCH * 2048];
    const __half* Ysrc = g_Yp[src];
    const uint32_t base = (uint32_t)__cvta_generic_to_shared(sBuf);

    // cp.async granule mapping (3 x 16B per thread per chunk)
    const int gA_c = (t >> 1) & 63, gA_s = t & 1;
    const int gY_h = (t >> 6) & 1,  gY_m = (t >> 1) & 31, gY_s = t & 1;
    const uint32_t dA0 = ((0 * 64 + gA_c) * 24 + gA_s * 8) * 2;
    const uint32_t dA1 = ((1 * 64 + gA_c) * 24 + gA_s * 8) * 2;
    const uint32_t dY  = ((gY_h * 32 + gY_m) * 24 + gY_s * 8) * 2;
    const int sA0 = 0 * 1024 + gA_c * 16 + gA_s * 8;
    const int sA1 = 1 * 1024 + gA_c * 16 + gA_s * 8;
    const int sY  = gY_h * 512 + gY_m * 16 + gY_s * 8;

    // ldmatrix per-lane byte offsets (relative to stage A / Y bases)
    const int tl = lane >> 3, rl = lane & 7;
    const int aRow = w * 16 + ((tl & 1) << 3) + rl;
    const int aKo  = (tl >> 1) << 3;
    const uint32_t offAhi = (uint32_t)((aRow)      * 24 + aKo) * 2;
    const uint32_t offAlo = (uint32_t)((64 + aRow) * 24 + aKo) * 2;
    const int yM  = ((tl >> 1) << 3) + rl;
    const int yKo = (tl & 1) << 3;
    const uint32_t offYh0 = (uint32_t)((yM)           * 24 + yKo) * 2;
    const uint32_t offYh1 = (uint32_t)((yM + 16)      * 24 + yKo) * 2;
    const uint32_t offYl0 = (uint32_t)((32 + yM)      * 24 + yKo) * 2;
    const uint32_t offYl1 = (uint32_t)((32 + yM + 16) * 24 + yKo) * 2;

    auto issue = [&](int kc2) {
        int buf = kc2 % STAGES;
        const __half* ac = Asrc + (size_t)kc2 * 2048;
        const __half* yc = Ysrc + (size_t)kc2 * 1024;
        uint32_t ab = base + buf * STGB;        // A part
        uint32_t yb = ab + 6144;                // Y part
        cpa16(ab + dA0, ac + sA0);
        cpa16(ab + dA1, ac + sA1);
        cpa16(yb + dY,  yc + sY);
    };

    // prologue: STAGES-1 groups
    issue(kbeg);     asm volatile("cp.async.commit_group;");
    issue(kbeg + 1); asm volatile("cp.async.commit_group;");
    issue(kbeg + 2); asm volatile("cp.async.commit_group;");

    float Cm[4][4], Cs[4][4];
    #pragma unroll
    for (int j = 0; j < 4; j++)
        #pragma unroll
        for (int q = 0; q < 4; q++) { Cm[j][q] = 0.f; Cs[j][q] = 0.f; }

    for (int kc = kbeg; kc < kend; kc++) {
        asm volatile("cp.async.wait_group %0;" :: "n"(STAGES - 2));
        __syncthreads();
        int nkc = kc + STAGES - 1;
        if (nkc < kend) issue(nkc);
        asm volatile("cp.async.commit_group;");

        int buf = kc % STAGES;
        uint32_t ab = base + buf * STGB;
        uint32_t yb = ab + 6144;

        uint32_t Ah[4], Al[4], Bh0[4], Bh1[4], Bl0[4], Bl1[4];
        ldm4(Ah,  ab + offAhi);
        ldm4(Al,  ab + offAlo);
        ldm4(Bh0, yb + offYh0);
        ldm4(Bh1, yb + offYh1);
        ldm4(Bl0, yb + offYl0);
        ldm4(Bl1, yb + offYl1);

        mma_(Cm[0], Ah, Bh0[0], Bh0[1]);
        mma_(Cm[1], Ah, Bh0[2], Bh0[3]);
        mma_(Cm[2], Ah, Bh1[0], Bh1[1]);
        mma_(Cm[3], Ah, Bh1[2], Bh1[3]);

        mma_(Cs[0], Ah, Bl0[0], Bl0[1]);
        mma_(Cs[1], Ah, Bl0[2], Bl0[3]);
        mma_(Cs[2], Ah, Bl1[0], Bl1[1]);
        mma_(Cs[3], Ah, Bl1[2], Bl1[3]);

        mma_(Cs[0], Al, Bh0[0], Bh0[1]);
        mma_(Cs[1], Al, Bh0[2], Bh0[3]);
        mma_(Cs[2], Al, Bh1[0], Bh1[1]);
        mma_(Cs[3], Al, Bh1[2], Bh1[3]);
    }
    asm volatile("cp.async.wait_group 0;");
    __syncthreads();

    // scatter C frags -> sZ[c][m]  (sZ overlays the finished pipeline smem)
    float (*sZ)[33] = (float (*)[33])sBuf;
    {
        const int g = lane >> 2, i2 = (lane & 3) << 1;
        const int c = w * 16 + g;
        #pragma unroll
        for (int j = 0; j < 4; j++) {
            int m = j * 8 + i2;
            sZ[c][m]         = Cm[j][0] + Cs[j][0] * INV2048;
            sZ[c][m + 1]     = Cm[j][1] + Cs[j][1] * INV2048;
            sZ[c + 8][m]     = Cm[j][2] + Cs[j][2] * INV2048;
            sZ[c + 8][m + 1] = Cm[j][3] + Cs[j][3] * INV2048;
        }
    }
    __syncthreads();

    // store partial Z (coalesced float4)
    {
        float* gp = &g_Zp[((size_t)(sp * NB + nb)) * 2048];
        #pragma unroll
        for (int q = 0; q < 4; q++) {
            int idx = t * 16 + q * 4;
            int c = idx >> 5, m = idx & 31;
            float4 v = make_float4(sZ[c][m], sZ[c][m + 1], sZ[c][m + 2], sZ[c][m + 3]);
            *reinterpret_cast<float4*>(gp + idx) = v;
        }
    }
    __threadfence();
    __syncthreads();
    if (t == 0) {
        int old = atomicAdd(&g_cnt[nb], 1);
        sLast = (old == KSPLIT - 1);
    }
    __syncthreads();
    if (!sLast) return;

    // ---- ticket CTA: reduce partials + epilogue ----
    const int col = t >> 1, r0 = (t & 1) << 4;
    const int gcol = nb * BN + col;
    float z[16];
    #pragma unroll
    for (int q = 0; q < 4; q++) {
        float4 acc = make_float4(0.f, 0.f, 0.f, 0.f);
        #pragma unroll
        for (int s2 = 0; s2 < KSPLIT; s2++) {
            const float4* p = reinterpret_cast<const float4*>(
                &g_Zp[((size_t)(s2 * NB + nb)) * 2048 + col * 32 + r0 + q * 4]);
            float4 v = __ldcg(p);
            acc.x += v.x; acc.y += v.y; acc.z += v.z; acc.w += v.w;
        }
        z[q * 4 + 0] = acc.x; z[q * 4 + 1] = acc.y;
        z[q * 4 + 2] = acc.z; z[q * 4 + 3] = acc.w;
    }

    float* Bp = &g_B[(nb * BN + col) * MR];
    const bool writeOut = (it == fwv);
    const bool writeY   = (it < fwv);

    #pragma unroll
    for (int r = 0; r < 16; r++) {
        int rr = r0 + r;
        float zz = z[r];
        if (useB)   zz += Bp[rr];
        if (writeB) Bp[rr] = zz;
        float xv = fmaxf(zz, 0.0f);
        if (writeOut && gcol < NCOLS) out[(size_t)rr * NCOLS + gcol] = xv;
        sZ[col][rr] = xv;
    }
    __syncthreads();

    if (writeY) {
        int kc = gcol >> 4, kk = gcol & 15;
        __half* Yd = g_Yp[src ^ 1] + (size_t)kc * 1024;
        #pragma unroll
        for (int r = 0; r < 16; r++) {
            int rr = r0 + r;
            float y = 0.f;
            #pragma unroll
            for (int j = 0; j < MR; j++) y += sWp[rr * MR + j] * sZ[col][j];
            __half h, l; hilo(y, h, l);
            Yd[rr * 16 + kk] = h;
            Yd[512 + rr * 16 + kk] = l;
        }
    }
    if (t == 0) g_cnt[nb] = 0;   // reset for next pass / replay
}

// ---------------- launch ----------------
// Inputs: W, Omega_1, Omega_2, X_0, A, U, fw_mitr
extern "C" void kernel_launch(void* const* d_in, const int* in_sizes, int n_in,
                              void* d_out, int out_size) {
    const float* W   = (const float*)d_in[0];
    const float* Om1 = (const float*)d_in[1];
    const float* A   = (const float*)d_in[4];
    const float* U   = (const float*)d_in[5];
    const int*   fw  = (const int*)  d_in[6];
    float*       out = (float*)d_out;

    k_project<<<1, 32>>>(W);
    k_convA<<<NB * KCH, 128>>>(A);
    k_T<<<KCH, 128>>>(Om1, U);

    // it = 1: Z = T@A = b ; B := Z ; X1 = relu(b) ; Y1 = Wp@X1
    k_iter<<<NB * KSPLIT, 128>>>(fw, out, 1, 0, 1, 0);
    // it = 2..30
    for (int it = 2; it <= 30; it++)
        k_iter<<<NB * KSPLIT, 128>>>(fw, out, it, (it - 1) & 1, 0, 1);
}